// round 4
// baseline (speedup 1.0000x reference)
#include <cuda_runtime.h>

// DCT_18769007084406 — per-channel separable 8x8 DCT, YCbCr mix commuted to the
// epilogue, butterfly DCT, closed-form affine, software-pipelined channel loads.
// x[32,3,512,512] fp32 -> out[32,192,64,64] fp32

#define NT 256
#define PITCH 36                      // 36 % 32 == 4 -> conflict-free both stages
#define GF (24 * 8 * PITCH)           // 6912 floats

static __device__ constexpr float B4[8][4] = {
  { 0.35355339059327373f,  0.35355339059327373f,  0.35355339059327373f,  0.35355339059327373f },
  { 0.49039264020161522f,  0.41573480615127262f,  0.27778511650980114f,  0.09754516100806417f },
  { 0.46193976625564337f,  0.19134171618254492f, -0.19134171618254492f, -0.46193976625564337f },
  { 0.41573480615127262f, -0.09754516100806417f, -0.49039264020161522f, -0.27778511650980114f },
  { 0.35355339059327373f, -0.35355339059327373f, -0.35355339059327373f,  0.35355339059327373f },
  { 0.27778511650980114f, -0.49039264020161522f,  0.09754516100806417f,  0.41573480615127262f },
  { 0.19134171618254492f, -0.46193976625564337f,  0.46193976625564337f, -0.19134171618254492f },
  { 0.09754516100806417f, -0.27778511650980114f,  0.41573480615127262f, -0.49039264020161522f }
};

__global__ void __launch_bounds__(NT, 7)
dct_fused_kernel(const float* __restrict__ x,
                 const float* __restrict__ max_,
                 const float* __restrict__ min_,
                 const float* __restrict__ ycw,
                 float* __restrict__ out)
{
    __shared__ float  G[GF];          // [((c*8+u)*8 + j)*PITCH + bw]
    __shared__ float2 aff[192];

    const int t    = threadIdx.x;
    const int bx   = blockIdx.x;
    const int r    = bx >> 1;         // block-row 0..63
    const int half = bx & 1;          // 256-col half
    const int b    = blockIdx.y;

    if (t < 192) {
        const float mx = max_[b * 192 + t];
        const float mn = min_[b * 192 + t];
        const float d  = mx - mn + 1e-6f;
        const float rr = 1.0f / d;
        float r2 = rr * rr, r4 = r2 * r2, r8 = r4 * r4, r16 = r8 * r8;
        const float r32 = r16 * r16;
        aff[t] = make_float2(r32, -mn * (rr * (1.0f - r32) / (1.0f - rr)));
    }

    // ------- Stage A: pipelined per-channel loads + vertical DCT (butterfly)
    const float* xb = x + ((size_t)b * 3 * 512 + (size_t)r * 8) * 512 + half * 256;
    const int j  = t & 7;
    const int bw = t >> 3;            // 0..31

    float vcur[8];
    #pragma unroll
    for (int i = 0; i < 8; ++i)
        vcur[i] = __ldg(xb + i * 512 + t);

    #pragma unroll
    for (int c = 0; c < 3; ++c) {
        float vnext[8];
        if (c < 2) {
            #pragma unroll
            for (int i = 0; i < 8; ++i)
                vnext[i] = __ldg(xb + (c + 1) * 262144 + i * 512 + t);
        }

        const float s0 = vcur[0] + vcur[7], s1 = vcur[1] + vcur[6];
        const float s2 = vcur[2] + vcur[5], s3 = vcur[3] + vcur[4];
        const float d0 = vcur[0] - vcur[7], d1 = vcur[1] - vcur[6];
        const float d2 = vcur[2] - vcur[5], d3 = vcur[3] - vcur[4];

        float* Gc = G + (c * 64 + j) * PITCH + bw;
        #pragma unroll
        for (int u = 0; u < 8; u += 2) {
            float e = B4[u][0] * s0;
            e = fmaf(B4[u][1], s1, e);
            e = fmaf(B4[u][2], s2, e);
            e = fmaf(B4[u][3], s3, e);
            Gc[u * 8 * PITCH] = e;
            float o = B4[u + 1][0] * d0;
            o = fmaf(B4[u + 1][1], d1, o);
            o = fmaf(B4[u + 1][2], d2, o);
            o = fmaf(B4[u + 1][3], d3, o);
            Gc[(u + 1) * 8 * PITCH] = o;
        }

        if (c < 2) {
            #pragma unroll
            for (int i = 0; i < 8; ++i)
                vcur[i] = vnext[i];
        }
    }

    __syncthreads();

    // ------- Stage B: channel mix (j-domain) + horizontal DCT + affine -----
    const int bwB = t & 31;
    const int u   = t >> 5;           // 0..7
    const size_t outb = (size_t)b * 192 * 4096 + (size_t)r * 64 + half * 32 + bwB;

    #pragma unroll
    for (int q = 0; q < 3; ++q) {     // output (YCbCr) channel
        float m[8];
        #pragma unroll
        for (int c = 0; c < 3; ++c) {
            const float w = ycw[q * 3 + c];
            #pragma unroll
            for (int jj = 0; jj < 8; ++jj) {
                const float g = G[((c * 8 + u) * 8 + jj) * PITCH + bwB];
                m[jj] = (c == 0) ? w * g : fmaf(w, g, m[jj]);
            }
        }

        const float s0 = m[0] + m[7], s1 = m[1] + m[6], s2 = m[2] + m[5], s3 = m[3] + m[4];
        const float d0 = m[0] - m[7], d1 = m[1] - m[6], d2 = m[2] - m[5], d3 = m[3] - m[4];

        const int kbase = q * 64 + u * 8;
        #pragma unroll
        for (int vv = 0; vv < 8; vv += 2) {
            float e = B4[vv][0] * s0;
            e = fmaf(B4[vv][1], s1, e);
            e = fmaf(B4[vv][2], s2, e);
            e = fmaf(B4[vv][3], s3, e);
            float2 sb = aff[kbase + vv];
            out[outb + (size_t)(kbase + vv) * 4096] = fmaf(e, sb.x, sb.y);

            float o = B4[vv + 1][0] * d0;
            o = fmaf(B4[vv + 1][1], d1, o);
            o = fmaf(B4[vv + 1][2], d2, o);
            o = fmaf(B4[vv + 1][3], d3, o);
            sb = aff[kbase + vv + 1];
            out[outb + (size_t)(kbase + vv + 1) * 4096] = fmaf(o, sb.x, sb.y);
        }
    }
}

extern "C" void kernel_launch(void* const* d_in, const int* in_sizes, int n_in,
                              void* d_out, int out_size)
{
    const float* x    = (const float*)d_in[0];
    const float* max_ = (const float*)d_in[1];
    const float* min_ = (const float*)d_in[2];
    const float* ycw  = (const float*)d_in[3];
    float* out = (float*)d_out;

    dim3 grid(128, 32);
    dct_fused_kernel<<<grid, NT>>>(x, max_, min_, ycw, out);
}

// round 5
// speedup vs baseline: 1.2567x; 1.2567x over previous
#include <cuda_runtime.h>

// DCT_18769007084406 — per-channel separable 8x8 DCT, YCbCr mix in epilogue,
// butterfly DCT, closed-form affine. Stage A: 16 loads batched + 8 pipelined.
// x[32,3,512,512] fp32 -> out[32,192,64,64] fp32

#define NT 256
#define PITCH 36                      // 36 % 32 == 4 -> conflict-free both stages
#define GF (24 * 8 * PITCH)           // 6912 floats

static __device__ constexpr float B4[8][4] = {
  { 0.35355339059327373f,  0.35355339059327373f,  0.35355339059327373f,  0.35355339059327373f },
  { 0.49039264020161522f,  0.41573480615127262f,  0.27778511650980114f,  0.09754516100806417f },
  { 0.46193976625564337f,  0.19134171618254492f, -0.19134171618254492f, -0.46193976625564337f },
  { 0.41573480615127262f, -0.09754516100806417f, -0.49039264020161522f, -0.27778511650980114f },
  { 0.35355339059327373f, -0.35355339059327373f, -0.35355339059327373f,  0.35355339059327373f },
  { 0.27778511650980114f, -0.49039264020161522f,  0.09754516100806417f,  0.41573480615127262f },
  { 0.19134171618254492f, -0.46193976625564337f,  0.46193976625564337f, -0.19134171618254492f },
  { 0.09754516100806417f, -0.27778511650980114f,  0.41573480615127262f, -0.49039264020161522f }
};

__device__ __forceinline__ void butterfly_store(const float v0, const float v1,
                                                const float v2, const float v3,
                                                const float v4, const float v5,
                                                const float v6, const float v7,
                                                float* Gc)
{
    const float s0 = v0 + v7, s1 = v1 + v6, s2 = v2 + v5, s3 = v3 + v4;
    const float d0 = v0 - v7, d1 = v1 - v6, d2 = v2 - v5, d3 = v3 - v4;
    #pragma unroll
    for (int u = 0; u < 8; u += 2) {
        float e = B4[u][0] * s0;
        e = fmaf(B4[u][1], s1, e);
        e = fmaf(B4[u][2], s2, e);
        e = fmaf(B4[u][3], s3, e);
        Gc[u * 8 * PITCH] = e;
        float o = B4[u + 1][0] * d0;
        o = fmaf(B4[u + 1][1], d1, o);
        o = fmaf(B4[u + 1][2], d2, o);
        o = fmaf(B4[u + 1][3], d3, o);
        Gc[(u + 1) * 8 * PITCH] = o;
    }
}

__global__ void __launch_bounds__(NT, 5)
dct_fused_kernel(const float* __restrict__ x,
                 const float* __restrict__ max_,
                 const float* __restrict__ min_,
                 const float* __restrict__ ycw,
                 float* __restrict__ out)
{
    __shared__ float  G[GF];          // [((c*8+u)*8 + j)*PITCH + bw]
    __shared__ float2 aff[192];

    const int t    = threadIdx.x;
    const int bx   = blockIdx.x;
    const int r    = bx >> 1;         // block-row 0..63
    const int half = bx & 1;          // 256-col half
    const int b    = blockIdx.y;

    if (t < 192) {
        const float mx = max_[b * 192 + t];
        const float mn = min_[b * 192 + t];
        const float d  = mx - mn + 1e-6f;
        const float rr = 1.0f / d;
        float r2 = rr * rr, r4 = r2 * r2, r8 = r4 * r4, r16 = r8 * r8;
        const float r32 = r16 * r16;
        aff[t] = make_float2(r32, -mn * (rr * (1.0f - r32) / (1.0f - rr)));
    }

    // ---- Stage A: channels 0+1 batched (16 in flight), channel 2 pipelined
    const float* xb = x + ((size_t)b * 3 * 512 + (size_t)r * 8) * 512 + half * 256;
    const int j  = t & 7;
    const int bw = t >> 3;            // 0..31

    float v0[8], v1[8];
    #pragma unroll
    for (int i = 0; i < 8; ++i) v0[i] = __ldg(xb + i * 512 + t);
    #pragma unroll
    for (int i = 0; i < 8; ++i) v1[i] = __ldg(xb + 262144 + i * 512 + t);

    float* Gc = G + j * PITCH + bw;
    butterfly_store(v0[0], v0[1], v0[2], v0[3], v0[4], v0[5], v0[6], v0[7], Gc);

    // channel 2 loads into registers freed by channel 0
    float v2[8];
    #pragma unroll
    for (int i = 0; i < 8; ++i) v2[i] = __ldg(xb + 524288 + i * 512 + t);

    butterfly_store(v1[0], v1[1], v1[2], v1[3], v1[4], v1[5], v1[6], v1[7],
                    Gc + 64 * PITCH);
    butterfly_store(v2[0], v2[1], v2[2], v2[3], v2[4], v2[5], v2[6], v2[7],
                    Gc + 128 * PITCH);

    __syncthreads();

    // ------- Stage B: channel mix (j-domain) + horizontal DCT + affine -----
    const int bwB = t & 31;
    const int u   = t >> 5;           // 0..7
    const size_t outb = (size_t)b * 192 * 4096 + (size_t)r * 64 + half * 32 + bwB;

    #pragma unroll
    for (int q = 0; q < 3; ++q) {     // output (YCbCr) channel
        float m[8];
        #pragma unroll
        for (int c = 0; c < 3; ++c) {
            const float w = ycw[q * 3 + c];
            #pragma unroll
            for (int jj = 0; jj < 8; ++jj) {
                const float g = G[((c * 8 + u) * 8 + jj) * PITCH + bwB];
                m[jj] = (c == 0) ? w * g : fmaf(w, g, m[jj]);
            }
        }

        const float s0 = m[0] + m[7], s1 = m[1] + m[6], s2 = m[2] + m[5], s3 = m[3] + m[4];
        const float d0 = m[0] - m[7], d1 = m[1] - m[6], d2 = m[2] - m[5], d3 = m[3] - m[4];

        const int kbase = q * 64 + u * 8;
        #pragma unroll
        for (int vv = 0; vv < 8; vv += 2) {
            float e = B4[vv][0] * s0;
            e = fmaf(B4[vv][1], s1, e);
            e = fmaf(B4[vv][2], s2, e);
            e = fmaf(B4[vv][3], s3, e);
            float2 sb = aff[kbase + vv];
            out[outb + (size_t)(kbase + vv) * 4096] = fmaf(e, sb.x, sb.y);

            float o = B4[vv + 1][0] * d0;
            o = fmaf(B4[vv + 1][1], d1, o);
            o = fmaf(B4[vv + 1][2], d2, o);
            o = fmaf(B4[vv + 1][3], d3, o);
            sb = aff[kbase + vv + 1];
            out[outb + (size_t)(kbase + vv + 1) * 4096] = fmaf(o, sb.x, sb.y);
        }
    }
}

extern "C" void kernel_launch(void* const* d_in, const int* in_sizes, int n_in,
                              void* d_out, int out_size)
{
    const float* x    = (const float*)d_in[0];
    const float* max_ = (const float*)d_in[1];
    const float* min_ = (const float*)d_in[2];
    const float* ycw  = (const float*)d_in[3];
    float* out = (float*)d_out;

    dim3 grid(128, 32);
    dct_fused_kernel<<<grid, NT>>>(x, max_, min_, ycw, out);
}

// round 7
// speedup vs baseline: 1.5781x; 1.2557x over previous
#include <cuda_runtime.h>

// DCT_18769007084406 — float4 loads, per-channel vertical DCT (4 cols/thread),
// YCbCr mix in epilogue, butterfly DCT, closed-form affine.
// x[32,3,512,512] fp32 -> out[32,192,64,64] fp32

#define NT 384
#define PITCH 68                      // 68 % 32 == 4 -> conflict-free both stages
#define GF (24 * 8 * PITCH)           // 13056 floats = 52224 B
#define SMEM_BYTES (GF * 4 + 192 * 8)

static __device__ constexpr float B4[8][4] = {
  { 0.35355339059327373f,  0.35355339059327373f,  0.35355339059327373f,  0.35355339059327373f },
  { 0.49039264020161522f,  0.41573480615127262f,  0.27778511650980114f,  0.09754516100806417f },
  { 0.46193976625564337f,  0.19134171618254492f, -0.19134171618254492f, -0.46193976625564337f },
  { 0.41573480615127262f, -0.09754516100806417f, -0.49039264020161522f, -0.27778511650980114f },
  { 0.35355339059327373f, -0.35355339059327373f, -0.35355339059327373f,  0.35355339059327373f },
  { 0.27778511650980114f, -0.49039264020161522f,  0.09754516100806417f,  0.41573480615127262f },
  { 0.19134171618254492f, -0.46193976625564337f,  0.46193976625564337f, -0.19134171618254492f },
  { 0.09754516100806417f, -0.27778511650980114f,  0.41573480615127262f, -0.49039264020161522f }
};

__global__ void __launch_bounds__(NT, 3)
dct_fused_kernel(const float* __restrict__ x,
                 const float* __restrict__ max_,
                 const float* __restrict__ min_,
                 const float* __restrict__ ycw,
                 float* __restrict__ out)
{
    extern __shared__ float sm[];
    float*  G   = sm;                 // [(c*64 + u*8 + j)*PITCH + bw]
    float2* aff = (float2*)(sm + GF);

    const int t = threadIdx.x;
    const int r = blockIdx.x;         // block-row 0..63
    const int b = blockIdx.y;         // batch

    if (t < 192) {
        const float mx = max_[b * 192 + t];
        const float mn = min_[b * 192 + t];
        const float d  = mx - mn + 1e-6f;
        const float rr = 1.0f / d;
        float r2 = rr * rr, r4 = r2 * r2, r8 = r4 * r4, r16 = r8 * r8;
        const float r32 = r16 * r16;
        aff[t] = make_float2(r32, -mn * (rr * (1.0f - r32) / (1.0f - rr)));
    }

    // ---- Stage A: one (channel, 4-col group) per thread, 8x LDG.128 -------
    const int c  = t >> 7;            // 0..2
    const int cg = t & 127;           // 4-col group 0..127; cols cg*4..cg*4+3
    const int j0 = (cg & 1) * 4;      // col%8 base: 0 or 4
    const int bw = cg >> 1;           // block-col 0..63

    const float4* xr = (const float4*)(x + ((size_t)b * 3 + c) * 262144
                                         + (size_t)r * 8 * 512) + cg;

    float4 v[8];
    #pragma unroll
    for (int i = 0; i < 8; ++i)
        v[i] = __ldg(xr + i * 128);   // 512 floats = 128 float4 per row

    const float4 s0 = make_float4(v[0].x + v[7].x, v[0].y + v[7].y, v[0].z + v[7].z, v[0].w + v[7].w);
    const float4 d0 = make_float4(v[0].x - v[7].x, v[0].y - v[7].y, v[0].z - v[7].z, v[0].w - v[7].w);
    const float4 s1 = make_float4(v[1].x + v[6].x, v[1].y + v[6].y, v[1].z + v[6].z, v[1].w + v[6].w);
    const float4 d1 = make_float4(v[1].x - v[6].x, v[1].y - v[6].y, v[1].z - v[6].z, v[1].w - v[6].w);
    const float4 s2 = make_float4(v[2].x + v[5].x, v[2].y + v[5].y, v[2].z + v[5].z, v[2].w + v[5].w);
    const float4 d2 = make_float4(v[2].x - v[5].x, v[2].y - v[5].y, v[2].z - v[5].z, v[2].w - v[5].w);
    const float4 s3 = make_float4(v[3].x + v[4].x, v[3].y + v[4].y, v[3].z + v[4].z, v[3].w + v[4].w);
    const float4 d3 = make_float4(v[3].x - v[4].x, v[3].y - v[4].y, v[3].z - v[4].z, v[3].w - v[4].w);

    // row index = c*64 + u*8 + (j0 + l)   (FIX: channel stride is 64 rows)
    float* Gc = G + (c * 64 + j0) * PITCH + bw;
    #pragma unroll
    for (int u = 0; u < 8; u += 2) {
        float4 e;
        e.x = fmaf(B4[u][0], s0.x, fmaf(B4[u][1], s1.x, fmaf(B4[u][2], s2.x, B4[u][3] * s3.x)));
        e.y = fmaf(B4[u][0], s0.y, fmaf(B4[u][1], s1.y, fmaf(B4[u][2], s2.y, B4[u][3] * s3.y)));
        e.z = fmaf(B4[u][0], s0.z, fmaf(B4[u][1], s1.z, fmaf(B4[u][2], s2.z, B4[u][3] * s3.z)));
        e.w = fmaf(B4[u][0], s0.w, fmaf(B4[u][1], s1.w, fmaf(B4[u][2], s2.w, B4[u][3] * s3.w)));
        float* Gu = Gc + u * 8 * PITCH;
        Gu[0 * PITCH] = e.x;  Gu[1 * PITCH] = e.y;
        Gu[2 * PITCH] = e.z;  Gu[3 * PITCH] = e.w;

        float4 o;
        o.x = fmaf(B4[u+1][0], d0.x, fmaf(B4[u+1][1], d1.x, fmaf(B4[u+1][2], d2.x, B4[u+1][3] * d3.x)));
        o.y = fmaf(B4[u+1][0], d0.y, fmaf(B4[u+1][1], d1.y, fmaf(B4[u+1][2], d2.y, B4[u+1][3] * d3.y)));
        o.z = fmaf(B4[u+1][0], d0.z, fmaf(B4[u+1][1], d1.z, fmaf(B4[u+1][2], d2.z, B4[u+1][3] * d3.z)));
        o.w = fmaf(B4[u+1][0], d0.w, fmaf(B4[u+1][1], d1.w, fmaf(B4[u+1][2], d2.w, B4[u+1][3] * d3.w)));
        float* Go = Gc + (u + 1) * 8 * PITCH;
        Go[0 * PITCH] = o.x;  Go[1 * PITCH] = o.y;
        Go[2 * PITCH] = o.z;  Go[3 * PITCH] = o.w;
    }

    __syncthreads();

    // ------- Stage B: channel mix (j-domain) + horizontal DCT + affine -----
    const int bwB = t & 63;           // 0..63
    const int cu0 = t >> 6;           // 0..5
    const size_t outb = (size_t)b * 192 * 4096 + (size_t)r * 64 + bwB;

    #pragma unroll
    for (int q = 0; q < 4; ++q) {
        const int cu = cu0 + q * 6;   // 0..23 == c*8 + u
        const int uu = cu & 7, cc = cu >> 3;

        float m[8];
        #pragma unroll
        for (int ci = 0; ci < 3; ++ci) {
            const float w = ycw[cc * 3 + ci];
            #pragma unroll
            for (int jj = 0; jj < 8; ++jj) {
                const float g = G[((ci * 8 + uu) * 8 + jj) * PITCH + bwB];
                m[jj] = (ci == 0) ? w * g : fmaf(w, g, m[jj]);
            }
        }

        const float s0b = m[0] + m[7], s1b = m[1] + m[6], s2b = m[2] + m[5], s3b = m[3] + m[4];
        const float d0b = m[0] - m[7], d1b = m[1] - m[6], d2b = m[2] - m[5], d3b = m[3] - m[4];

        const int kbase = cu * 8;     // k = c*64 + u*8 + v
        #pragma unroll
        for (int vv = 0; vv < 8; vv += 2) {
            float e = B4[vv][0] * s0b;
            e = fmaf(B4[vv][1], s1b, e);
            e = fmaf(B4[vv][2], s2b, e);
            e = fmaf(B4[vv][3], s3b, e);
            float2 sb = aff[kbase + vv];
            out[outb + (size_t)(kbase + vv) * 4096] = fmaf(e, sb.x, sb.y);

            float o = B4[vv + 1][0] * d0b;
            o = fmaf(B4[vv + 1][1], d1b, o);
            o = fmaf(B4[vv + 1][2], d2b, o);
            o = fmaf(B4[vv + 1][3], d3b, o);
            sb = aff[kbase + vv + 1];
            out[outb + (size_t)(kbase + vv + 1) * 4096] = fmaf(o, sb.x, sb.y);
        }
    }
}

extern "C" void kernel_launch(void* const* d_in, const int* in_sizes, int n_in,
                              void* d_out, int out_size)
{
    const float* x    = (const float*)d_in[0];
    const float* max_ = (const float*)d_in[1];
    const float* min_ = (const float*)d_in[2];
    const float* ycw  = (const float*)d_in[3];
    float* out = (float*)d_out;

    cudaFuncSetAttribute(dct_fused_kernel,
                         cudaFuncAttributeMaxDynamicSharedMemorySize, SMEM_BYTES);

    dim3 grid(64, 32);                // (block-row, batch)
    dct_fused_kernel<<<grid, NT, SMEM_BYTES>>>(x, max_, min_, ycw, out);
}